// round 2
// baseline (speedup 1.0000x reference)
#include <cuda_runtime.h>

#define NN 100000
#define DD 64

// Scratch (static device globals; no runtime allocation).
// Y layout: [0]=x_drug@W_dd  [1]=x_drug@W_dg  [2]=x_gene@W_gd  [3]=x_gene@W_gg
// acc/deg layout (per relation, by dst): [0]=dd(drug) [1]=gd(drug) [2]=dg(gene) [3]=gg(gene)
__device__ float g_Y[4ull * NN * DD];
__device__ float g_acc[4ull * NN * DD];
__device__ float g_deg[4ull * NN];

// ---------------------------------------------------------------------------
// Zero accumulators + degree counters (must run every launch: graph replays).
// ---------------------------------------------------------------------------
__global__ void zero_kernel() {
    const int total4 = 4 * NN * DD / 4;  // 6,400,000 float4
    float4 z = make_float4(0.f, 0.f, 0.f, 0.f);
    int stride = gridDim.x * blockDim.x;
    for (int i = blockIdx.x * blockDim.x + threadIdx.x; i < total4; i += stride)
        reinterpret_cast<float4*>(g_acc)[i] = z;
    for (int i = blockIdx.x * blockDim.x + threadIdx.x; i < 4 * NN; i += stride)
        g_deg[i] = 0.f;
}

// ---------------------------------------------------------------------------
// Projection GEMM: for each src type, compute both [N,64]@[64,64] products in
// one pass over x. Block = 32 rows x 128 cols (two W's concatenated in smem).
// Thread (rg, col) computes 16 rows of one output column; x reads are
// warp-broadcast float4 LDS, W reads are conflict-free stride-1 LDS.
// ---------------------------------------------------------------------------
__global__ __launch_bounds__(256) void gemm_kernel(
    const float* __restrict__ xd, const float* __restrict__ xg,
    const float* __restrict__ Wdd, const float* __restrict__ Wdg,
    const float* __restrict__ Wgd, const float* __restrict__ Wgg) {
    __shared__ float Ws[64][128];   // [k][col], cols 0..63 -> W1, 64..127 -> W2
    __shared__ float xs[32][68];    // padded row stride (272B, 16B-aligned)

    const int t = blockIdx.y;  // 0 = drug src, 1 = gene src
    const float* x  = t ? xg  : xd;
    const float* W1 = t ? Wgd : Wdd;
    const float* W2 = t ? Wgg : Wdg;
    float* Y1 = g_Y + (t ? 2ull : 0ull) * NN * DD;
    float* Y2 = g_Y + (t ? 3ull : 1ull) * NN * DD;

    const int tid = threadIdx.x;
    for (int i = tid; i < 64 * 128; i += 256) {
        int k = i >> 7, c = i & 127;
        Ws[k][c] = (c < 64) ? W1[k * 64 + c] : W2[k * 64 + (c - 64)];
    }
    const long r0 = (long)blockIdx.x * 32;  // N = 3125 * 32, no tail
    for (int i = tid; i < 32 * 64; i += 256) {
        int r = i >> 6, k = i & 63;
        xs[r][k] = x[(r0 + r) * 64 + k];
    }
    __syncthreads();

    const int col = tid & 127;
    const int rg  = (tid >> 7) * 16;  // row group base: 0 or 16

    float acc[16];
#pragma unroll
    for (int r = 0; r < 16; r++) acc[r] = 0.f;

#pragma unroll 4
    for (int kk = 0; kk < 16; kk++) {
        float w0 = Ws[4 * kk + 0][col];
        float w1 = Ws[4 * kk + 1][col];
        float w2 = Ws[4 * kk + 2][col];
        float w3 = Ws[4 * kk + 3][col];
#pragma unroll
        for (int r = 0; r < 16; r++) {
            float4 xv = *reinterpret_cast<const float4*>(&xs[rg + r][4 * kk]);
            acc[r] = fmaf(xv.x, w0, acc[r]);
            acc[r] = fmaf(xv.y, w1, acc[r]);
            acc[r] = fmaf(xv.z, w2, acc[r]);
            acc[r] = fmaf(xv.w, w3, acc[r]);
        }
    }

    float* Y = (col < 64) ? Y1 : Y2;
    const int c = col & 63;
#pragma unroll
    for (int r = 0; r < 16; r++)
        Y[(r0 + rg + r) * 64 + c] = acc[r];
}

// ---------------------------------------------------------------------------
// Edge scatter: one warp per edge. Gather projected src row (float2/lane,
// L2-resident), RED.F32 into the per-relation dst accumulator + degree.
// ---------------------------------------------------------------------------
__global__ __launch_bounds__(256) void scatter_kernel(
    const int* __restrict__ src_dd, const int* __restrict__ dst_dd,
    const int* __restrict__ src_dg, const int* __restrict__ dst_dg,
    const int* __restrict__ src_gd, const int* __restrict__ dst_gd,
    const int* __restrict__ src_gg, const int* __restrict__ dst_gg,
    int n_edges) {
    const int rel = blockIdx.y;
    const long e = (long)blockIdx.x * 8 + (threadIdx.x >> 5);
    if (e >= n_edges) return;
    const int lane = threadIdx.x & 31;

    const int* src; const int* dst; const float* Y; float* acc; float* deg;
    switch (rel) {
        case 0:  src = src_dd; dst = dst_dd; Y = g_Y;                  acc = g_acc;                  deg = g_deg;          break;
        case 1:  src = src_gd; dst = dst_gd; Y = g_Y + 2ull * NN * DD; acc = g_acc + 1ull * NN * DD; deg = g_deg + NN;     break;
        case 2:  src = src_dg; dst = dst_dg; Y = g_Y + 1ull * NN * DD; acc = g_acc + 2ull * NN * DD; deg = g_deg + 2 * NN; break;
        default: src = src_gg; dst = dst_gg; Y = g_Y + 3ull * NN * DD; acc = g_acc + 3ull * NN * DD; deg = g_deg + 3 * NN; break;
    }

    const int s = __ldg(src + e);
    const int d = __ldg(dst + e);

    float2 v = *reinterpret_cast<const float2*>(Y + (size_t)s * DD + lane * 2);
    float* ap = acc + (size_t)d * DD + lane * 2;
    atomicAdd(ap,     v.x);
    atomicAdd(ap + 1, v.y);
    if (lane == 0) atomicAdd(deg + d, 1.0f);
}

// ---------------------------------------------------------------------------
// Finalize: out[type][n][c] = relu(acc_a/deg_a + acc_b/deg_b + bias), float4.
// ---------------------------------------------------------------------------
__global__ __launch_bounds__(256) void finalize_kernel(
    const float* __restrict__ bias, float* __restrict__ out) {
    const int per_type = NN * (DD / 4);  // 1,600,000 float4
    int i = blockIdx.x * blockDim.x + threadIdx.x;
    if (i >= 2 * per_type) return;

    const int type = (i >= per_type) ? 1 : 0;
    const int j = type ? i - per_type : i;
    const int n  = j >> 4;
    const int c4 = j & 15;

    const float4* a0; const float4* a1;
    float dg0, dg1;
    if (!type) {
        a0 = reinterpret_cast<const float4*>(g_acc);
        a1 = reinterpret_cast<const float4*>(g_acc + 1ull * NN * DD);
        dg0 = g_deg[n];
        dg1 = g_deg[NN + n];
    } else {
        a0 = reinterpret_cast<const float4*>(g_acc + 2ull * NN * DD);
        a1 = reinterpret_cast<const float4*>(g_acc + 3ull * NN * DD);
        dg0 = g_deg[2 * NN + n];
        dg1 = g_deg[3 * NN + n];
    }
    const float i0 = 1.f / fmaxf(dg0, 1.f);
    const float i1 = 1.f / fmaxf(dg1, 1.f);

    float4 v0 = a0[j];
    float4 v1 = a1[j];
    float4 b  = reinterpret_cast<const float4*>(bias)[c4];
    float4 o;
    o.x = fmaxf(fmaf(v0.x, i0, fmaf(v1.x, i1, b.x)), 0.f);
    o.y = fmaxf(fmaf(v0.y, i0, fmaf(v1.y, i1, b.y)), 0.f);
    o.z = fmaxf(fmaf(v0.z, i0, fmaf(v1.z, i1, b.z)), 0.f);
    o.w = fmaxf(fmaf(v0.w, i0, fmaf(v1.w, i1, b.w)), 0.f);
    reinterpret_cast<float4*>(out)[i] = o;
}

// ---------------------------------------------------------------------------
extern "C" void kernel_launch(void* const* d_in, const int* in_sizes, int n_in,
                              void* d_out, int out_size) {
    const float* xd   = (const float*)d_in[0];
    const float* xg   = (const float*)d_in[1];
    const float* Wdd  = (const float*)d_in[2];
    const float* Wdg  = (const float*)d_in[3];
    const float* Wgd  = (const float*)d_in[4];
    const float* Wgg  = (const float*)d_in[5];
    const float* bias = (const float*)d_in[6];
    const int* src_dd = (const int*)d_in[7];
    const int* dst_dd = (const int*)d_in[8];
    const int* src_dg = (const int*)d_in[9];
    const int* dst_dg = (const int*)d_in[10];
    const int* src_gd = (const int*)d_in[11];
    const int* dst_gd = (const int*)d_in[12];
    const int* src_gg = (const int*)d_in[13];
    const int* dst_gg = (const int*)d_in[14];
    float* out = (float*)d_out;

    const int n_edges = in_sizes[7];  // all four relations share E

    zero_kernel<<<8192, 256>>>();
    gemm_kernel<<<dim3(NN / 32, 2), 256>>>(xd, xg, Wdd, Wdg, Wgd, Wgg);
    scatter_kernel<<<dim3((n_edges + 7) / 8, 4), 256>>>(
        src_dd, dst_dd, src_dg, dst_dg, src_gd, dst_gd, src_gg, dst_gg, n_edges);
    finalize_kernel<<<(2 * NN * DD / 4 + 255) / 256, 256>>>(bias, out);
}

// round 3
// speedup vs baseline: 1.3770x; 1.3770x over previous
#include <cuda_runtime.h>

#define NN 100000
#define DD 64

// Scratch (static device globals; no runtime allocation).
// Y layout: [0]=x_drug@W_dd  [1]=x_drug@W_dg  [2]=x_gene@W_gd  [3]=x_gene@W_gg
// acc/deg layout (per relation, by dst): [0]=dd(drug) [1]=gd(drug) [2]=dg(gene) [3]=gg(gene)
__device__ float g_Y[4ull * NN * DD];
__device__ float g_acc[4ull * NN * DD];
__device__ float g_deg[4ull * NN];

// ---------------------------------------------------------------------------
// Zero accumulators + degree counters (must run every launch: graph replays).
// ---------------------------------------------------------------------------
__global__ void zero_kernel() {
    const int total4 = 4 * NN * DD / 4;  // 6,400,000 float4
    float4 z = make_float4(0.f, 0.f, 0.f, 0.f);
    int stride = gridDim.x * blockDim.x;
    for (int i = blockIdx.x * blockDim.x + threadIdx.x; i < total4; i += stride)
        reinterpret_cast<float4*>(g_acc)[i] = z;
    for (int i = blockIdx.x * blockDim.x + threadIdx.x; i < 4 * NN; i += stride)
        g_deg[i] = 0.f;
}

// ---------------------------------------------------------------------------
// Projection GEMM: for each src type, compute both [N,64]@[64,64] products in
// one pass over x. Block = 32 rows x 128 cols (two W's concatenated in smem).
// ---------------------------------------------------------------------------
__global__ __launch_bounds__(256) void gemm_kernel(
    const float* __restrict__ xd, const float* __restrict__ xg,
    const float* __restrict__ Wdd, const float* __restrict__ Wdg,
    const float* __restrict__ Wgd, const float* __restrict__ Wgg) {
    __shared__ float Ws[64][128];   // [k][col], cols 0..63 -> W1, 64..127 -> W2
    __shared__ float xs[32][68];    // padded row stride

    const int t = blockIdx.y;  // 0 = drug src, 1 = gene src
    const float* x  = t ? xg  : xd;
    const float* W1 = t ? Wgd : Wdd;
    const float* W2 = t ? Wgg : Wdg;
    float* Y1 = g_Y + (t ? 2ull : 0ull) * NN * DD;
    float* Y2 = g_Y + (t ? 3ull : 1ull) * NN * DD;

    const int tid = threadIdx.x;
    for (int i = tid; i < 64 * 128; i += 256) {
        int k = i >> 7, c = i & 127;
        Ws[k][c] = (c < 64) ? W1[k * 64 + c] : W2[k * 64 + (c - 64)];
    }
    const long r0 = (long)blockIdx.x * 32;  // N = 3125 * 32, no tail
    for (int i = tid; i < 32 * 64; i += 256) {
        int r = i >> 6, k = i & 63;
        xs[r][k] = x[(r0 + r) * 64 + k];
    }
    __syncthreads();

    const int col = tid & 127;
    const int rg  = (tid >> 7) * 16;  // row group base: 0 or 16

    float acc[16];
#pragma unroll
    for (int r = 0; r < 16; r++) acc[r] = 0.f;

#pragma unroll 4
    for (int kk = 0; kk < 16; kk++) {
        float w0 = Ws[4 * kk + 0][col];
        float w1 = Ws[4 * kk + 1][col];
        float w2 = Ws[4 * kk + 2][col];
        float w3 = Ws[4 * kk + 3][col];
#pragma unroll
        for (int r = 0; r < 16; r++) {
            float4 xv = *reinterpret_cast<const float4*>(&xs[rg + r][4 * kk]);
            acc[r] = fmaf(xv.x, w0, acc[r]);
            acc[r] = fmaf(xv.y, w1, acc[r]);
            acc[r] = fmaf(xv.z, w2, acc[r]);
            acc[r] = fmaf(xv.w, w3, acc[r]);
        }
    }

    float* Y = (col < 64) ? Y1 : Y2;
    const int c = col & 63;
#pragma unroll
    for (int r = 0; r < 16; r++)
        Y[(r0 + rg + r) * 64 + c] = acc[r];
}

// ---------------------------------------------------------------------------
// Edge scatter: 16 lanes per edge, each lane owns 4 floats. Gather one float4
// (L2-resident) and issue ONE red.global.add.v4.f32 per lane -> 16 vector
// atomics per edge instead of 64 scalar ones.
// ---------------------------------------------------------------------------
__global__ __launch_bounds__(256) void scatter_kernel(
    const int* __restrict__ src_dd, const int* __restrict__ dst_dd,
    const int* __restrict__ src_dg, const int* __restrict__ dst_dg,
    const int* __restrict__ src_gd, const int* __restrict__ dst_gd,
    const int* __restrict__ src_gg, const int* __restrict__ dst_gg,
    int n_edges) {
    const int rel = blockIdx.y;
    const long e = (long)blockIdx.x * 16 + (threadIdx.x >> 4);
    if (e >= n_edges) return;
    const int lane = threadIdx.x & 15;

    const int* src; const int* dst; const float* Y; float* acc; float* deg;
    switch (rel) {
        case 0:  src = src_dd; dst = dst_dd; Y = g_Y;                  acc = g_acc;                  deg = g_deg;          break;
        case 1:  src = src_gd; dst = dst_gd; Y = g_Y + 2ull * NN * DD; acc = g_acc + 1ull * NN * DD; deg = g_deg + NN;     break;
        case 2:  src = src_dg; dst = dst_dg; Y = g_Y + 1ull * NN * DD; acc = g_acc + 2ull * NN * DD; deg = g_deg + 2 * NN; break;
        default: src = src_gg; dst = dst_gg; Y = g_Y + 3ull * NN * DD; acc = g_acc + 3ull * NN * DD; deg = g_deg + 3 * NN; break;
    }

    const int s = __ldg(src + e);
    const int d = __ldg(dst + e);

    float4 v = *reinterpret_cast<const float4*>(Y + (size_t)s * DD + lane * 4);
    float* ap = acc + (size_t)d * DD + lane * 4;
    asm volatile("red.global.add.v4.f32 [%0], {%1, %2, %3, %4};"
                 :: "l"(ap), "f"(v.x), "f"(v.y), "f"(v.z), "f"(v.w)
                 : "memory");
    if (lane == 0) atomicAdd(deg + d, 1.0f);
}

// ---------------------------------------------------------------------------
// Finalize: out[type][n][c] = relu(acc_a/deg_a + acc_b/deg_b + bias), float4.
// ---------------------------------------------------------------------------
__global__ __launch_bounds__(256) void finalize_kernel(
    const float* __restrict__ bias, float* __restrict__ out) {
    const int per_type = NN * (DD / 4);  // 1,600,000 float4
    int i = blockIdx.x * blockDim.x + threadIdx.x;
    if (i >= 2 * per_type) return;

    const int type = (i >= per_type) ? 1 : 0;
    const int j = type ? i - per_type : i;
    const int n  = j >> 4;
    const int c4 = j & 15;

    const float4* a0; const float4* a1;
    float dg0, dg1;
    if (!type) {
        a0 = reinterpret_cast<const float4*>(g_acc);
        a1 = reinterpret_cast<const float4*>(g_acc + 1ull * NN * DD);
        dg0 = g_deg[n];
        dg1 = g_deg[NN + n];
    } else {
        a0 = reinterpret_cast<const float4*>(g_acc + 2ull * NN * DD);
        a1 = reinterpret_cast<const float4*>(g_acc + 3ull * NN * DD);
        dg0 = g_deg[2 * NN + n];
        dg1 = g_deg[3 * NN + n];
    }
    const float i0 = 1.f / fmaxf(dg0, 1.f);
    const float i1 = 1.f / fmaxf(dg1, 1.f);

    float4 v0 = a0[j];
    float4 v1 = a1[j];
    float4 b  = reinterpret_cast<const float4*>(bias)[c4];
    float4 o;
    o.x = fmaxf(fmaf(v0.x, i0, fmaf(v1.x, i1, b.x)), 0.f);
    o.y = fmaxf(fmaf(v0.y, i0, fmaf(v1.y, i1, b.y)), 0.f);
    o.z = fmaxf(fmaf(v0.z, i0, fmaf(v1.z, i1, b.z)), 0.f);
    o.w = fmaxf(fmaf(v0.w, i0, fmaf(v1.w, i1, b.w)), 0.f);
    reinterpret_cast<float4*>(out)[i] = o;
}

// ---------------------------------------------------------------------------
extern "C" void kernel_launch(void* const* d_in, const int* in_sizes, int n_in,
                              void* d_out, int out_size) {
    const float* xd   = (const float*)d_in[0];
    const float* xg   = (const float*)d_in[1];
    const float* Wdd  = (const float*)d_in[2];
    const float* Wdg  = (const float*)d_in[3];
    const float* Wgd  = (const float*)d_in[4];
    const float* Wgg  = (const float*)d_in[5];
    const float* bias = (const float*)d_in[6];
    const int* src_dd = (const int*)d_in[7];
    const int* dst_dd = (const int*)d_in[8];
    const int* src_dg = (const int*)d_in[9];
    const int* dst_dg = (const int*)d_in[10];
    const int* src_gd = (const int*)d_in[11];
    const int* dst_gd = (const int*)d_in[12];
    const int* src_gg = (const int*)d_in[13];
    const int* dst_gg = (const int*)d_in[14];
    float* out = (float*)d_out;

    const int n_edges = in_sizes[7];  // all four relations share E

    zero_kernel<<<8192, 256>>>();
    gemm_kernel<<<dim3(NN / 32, 2), 256>>>(xd, xg, Wdd, Wdg, Wgd, Wgg);
    scatter_kernel<<<dim3((n_edges + 15) / 16, 4), 256>>>(
        src_dd, dst_dd, src_dg, dst_dg, src_gd, dst_gd, src_gg, dst_gg, n_edges);
    finalize_kernel<<<(2 * NN * DD / 4 + 255) / 256, 256>>>(bias, out);
}

// round 5
// speedup vs baseline: 1.8311x; 1.3298x over previous
#include <cuda_runtime.h>

#define NN 100000
#define DD 64
#define EMAX 800000
#define TOT (4 * NN)          // total count slots
#define NB ((TOT + 1023) / 1024)  // scan blocks = 391

// Scratch (static device globals; no runtime allocation).
// Y layout: [0]=x_drug@W_dd  [1]=x_drug@W_dg  [2]=x_gene@W_gd  [3]=x_gene@W_gg
// slot layout (by dst): 0=dd(drug) 1=gd(drug) 2=dg(gene) 3=gg(gene)
__device__ float g_Y[4ull * NN * DD];
__device__ int   g_cnt[TOT];      // per-(slot,dst) degree
__device__ int   g_incl[TOT];     // block-inclusive scan
__device__ int   g_base[TOT];     // exclusive offsets; after scatter_perm = end offsets
__device__ int   g_bsum[512];     // per-block totals
__device__ int   g_bbase[512];    // exclusive block bases
__device__ int   g_psrc[4ull * EMAX];  // src indices sorted by (slot, dst)

// ---------------------------------------------------------------------------
__global__ void zero_cnt_kernel() {
    int i = blockIdx.x * blockDim.x + threadIdx.x;
    if (i < TOT) g_cnt[i] = 0;
}

// ---------------------------------------------------------------------------
// Projection GEMM: both [N,64]@[64,64] per src type in one pass.
// ---------------------------------------------------------------------------
__global__ __launch_bounds__(256) void gemm_kernel(
    const float* __restrict__ xd, const float* __restrict__ xg,
    const float* __restrict__ Wdd, const float* __restrict__ Wdg,
    const float* __restrict__ Wgd, const float* __restrict__ Wgg) {
    __shared__ float Ws[64][128];
    __shared__ float xs[32][68];

    const int t = blockIdx.y;  // 0 = drug src, 1 = gene src
    const float* x  = t ? xg  : xd;
    const float* W1 = t ? Wgd : Wdd;
    const float* W2 = t ? Wgg : Wdg;
    float* Y1 = g_Y + (t ? 2ull : 0ull) * NN * DD;
    float* Y2 = g_Y + (t ? 3ull : 1ull) * NN * DD;

    const int tid = threadIdx.x;
    for (int i = tid; i < 64 * 128; i += 256) {
        int k = i >> 7, c = i & 127;
        Ws[k][c] = (c < 64) ? W1[k * 64 + c] : W2[k * 64 + (c - 64)];
    }
    const long r0 = (long)blockIdx.x * 32;  // N = 3125 * 32, no tail
    for (int i = tid; i < 32 * 64; i += 256) {
        int r = i >> 6, k = i & 63;
        xs[r][k] = x[(r0 + r) * 64 + k];
    }
    __syncthreads();

    const int col = tid & 127;
    const int rg  = (tid >> 7) * 16;

    float acc[16];
#pragma unroll
    for (int r = 0; r < 16; r++) acc[r] = 0.f;

#pragma unroll 4
    for (int kk = 0; kk < 16; kk++) {
        float w0 = Ws[4 * kk + 0][col];
        float w1 = Ws[4 * kk + 1][col];
        float w2 = Ws[4 * kk + 2][col];
        float w3 = Ws[4 * kk + 3][col];
#pragma unroll
        for (int r = 0; r < 16; r++) {
            float4 xv = *reinterpret_cast<const float4*>(&xs[rg + r][4 * kk]);
            acc[r] = fmaf(xv.x, w0, acc[r]);
            acc[r] = fmaf(xv.y, w1, acc[r]);
            acc[r] = fmaf(xv.z, w2, acc[r]);
            acc[r] = fmaf(xv.w, w3, acc[r]);
        }
    }

    float* Y = (col < 64) ? Y1 : Y2;
    const int c = col & 63;
#pragma unroll
    for (int r = 0; r < 16; r++)
        Y[(r0 + rg + r) * 64 + c] = acc[r];
}

// ---------------------------------------------------------------------------
// Counting sort, step 1: per-(slot,dst) histogram.
// ---------------------------------------------------------------------------
__global__ __launch_bounds__(256) void hist_kernel(
    const int* __restrict__ dst0, const int* __restrict__ dst1,
    const int* __restrict__ dst2, const int* __restrict__ dst3,
    int n_edges) {
    int e = blockIdx.x * 256 + threadIdx.x;
    if (e >= n_edges) return;
    const int slot = blockIdx.y;
    const int* dst = (slot == 0) ? dst0 : (slot == 1) ? dst1 : (slot == 2) ? dst2 : dst3;
    atomicAdd(&g_cnt[slot * NN + __ldg(dst + e)], 1);
}

// ---------------------------------------------------------------------------
// Step 2a: per-block inclusive scan (1024 elems/block) + block totals.
// ---------------------------------------------------------------------------
__global__ __launch_bounds__(1024) void scan_blocks_kernel() {
    __shared__ int s[1024];
    const int tid = threadIdx.x;
    const int i = blockIdx.x * 1024 + tid;
    int v = (i < TOT) ? g_cnt[i] : 0;
    s[tid] = v;
    __syncthreads();
#pragma unroll
    for (int off = 1; off < 1024; off <<= 1) {
        int t = (tid >= off) ? s[tid - off] : 0;
        __syncthreads();
        s[tid] += t;
        __syncthreads();
    }
    if (i < TOT) g_incl[i] = s[tid];
    if (tid == 1023) g_bsum[blockIdx.x] = s[1023];
}

// Step 2b: scan the 391 block totals (single block) -> exclusive block bases.
__global__ __launch_bounds__(512) void scan_partials_kernel() {
    __shared__ int s[512];
    const int tid = threadIdx.x;
    int v = (tid < NB) ? g_bsum[tid] : 0;
    s[tid] = v;
    __syncthreads();
#pragma unroll
    for (int off = 1; off < 512; off <<= 1) {
        int t = (tid >= off) ? s[tid - off] : 0;
        __syncthreads();
        s[tid] += t;
        __syncthreads();
    }
    g_bbase[tid] = s[tid] - v;  // exclusive
}

// Step 2c: global exclusive offset per slot-index.
__global__ __launch_bounds__(256) void add_base_kernel() {
    int i = blockIdx.x * 256 + threadIdx.x;
    if (i >= TOT) return;
    g_base[i] = g_bbase[i >> 10] + g_incl[i] - g_cnt[i];
}

// ---------------------------------------------------------------------------
// Step 3: scatter src indices into dst-sorted order. Afterwards g_base[idx]
// holds the END offset of segment idx (start = end - g_cnt[idx]).
// ---------------------------------------------------------------------------
__global__ __launch_bounds__(256) void scatter_perm_kernel(
    const int* __restrict__ src0, const int* __restrict__ dst0,
    const int* __restrict__ src1, const int* __restrict__ dst1,
    const int* __restrict__ src2, const int* __restrict__ dst2,
    const int* __restrict__ src3, const int* __restrict__ dst3,
    int n_edges) {
    int e = blockIdx.x * 256 + threadIdx.x;
    if (e >= n_edges) return;
    const int slot = blockIdx.y;
    const int* src; const int* dst;
    switch (slot) {
        case 0:  src = src0; dst = dst0; break;
        case 1:  src = src1; dst = dst1; break;
        case 2:  src = src2; dst = dst2; break;
        default: src = src3; dst = dst3; break;
    }
    const int s = __ldg(src + e);
    const int d = __ldg(dst + e);
    int pos = atomicAdd(&g_base[slot * NN + d], 1);
    g_psrc[pos] = s;
}

// ---------------------------------------------------------------------------
// Pull gather + fused normalize/sum/bias/relu/output.
// 16 lanes per node, each lane owns one float4. Two relation slots per dst
// type accumulated in registers, single write out. No atomics anywhere.
// ---------------------------------------------------------------------------
__global__ __launch_bounds__(256) void gather_kernel(
    const float* __restrict__ bias, float* __restrict__ out) {
    const int t = blockIdx.y;                       // 0=drug, 1=gene
    const int node = blockIdx.x * 16 + (threadIdx.x >> 4);
    const int lane = threadIdx.x & 15;
    // slot -> Y section: slots 0,1 feed drug (Y0=dd, Y2=gd); 2,3 feed gene (Y1=dg, Y3=gg)
    const float* YA = g_Y + (t ? 1ull : 0ull) * NN * DD;
    const float* YB = g_Y + (t ? 3ull : 2ull) * NN * DD;
    const int c0 = lane * 4;

    float4 res = make_float4(0.f, 0.f, 0.f, 0.f);

#pragma unroll
    for (int rel = 0; rel < 2; rel++) {
        const float* Y = rel ? YB : YA;
        const int idx = (2 * t + rel) * NN + node;
        const int deg = __ldg(g_cnt + idx);
        const int end = __ldg(g_base + idx);   // end offset (post scatter_perm)

        float4 a = make_float4(0.f, 0.f, 0.f, 0.f);
#pragma unroll 2
        for (int e = end - deg; e < end; e++) {
            int s = __ldg(g_psrc + e);
            float4 v = *reinterpret_cast<const float4*>(Y + (size_t)s * DD + c0);
            a.x += v.x; a.y += v.y; a.z += v.z; a.w += v.w;
        }
        const float inv = 1.f / (float)max(deg, 1);
        res.x = fmaf(a.x, inv, res.x);
        res.y = fmaf(a.y, inv, res.y);
        res.z = fmaf(a.z, inv, res.z);
        res.w = fmaf(a.w, inv, res.w);
    }

    float4 b = reinterpret_cast<const float4*>(bias)[lane];
    float4 o;
    o.x = fmaxf(res.x + b.x, 0.f);
    o.y = fmaxf(res.y + b.y, 0.f);
    o.z = fmaxf(res.z + b.z, 0.f);
    o.w = fmaxf(res.w + b.w, 0.f);
    *reinterpret_cast<float4*>(out + (size_t)t * NN * DD + (size_t)node * DD + c0) = o;
}

// ---------------------------------------------------------------------------
extern "C" void kernel_launch(void* const* d_in, const int* in_sizes, int n_in,
                              void* d_out, int out_size) {
    const float* xd   = (const float*)d_in[0];
    const float* xg   = (const float*)d_in[1];
    const float* Wdd  = (const float*)d_in[2];
    const float* Wdg  = (const float*)d_in[3];
    const float* Wgd  = (const float*)d_in[4];
    const float* Wgg  = (const float*)d_in[5];
    const float* bias = (const float*)d_in[6];
    const int* src_dd = (const int*)d_in[7];
    const int* dst_dd = (const int*)d_in[8];
    const int* src_dg = (const int*)d_in[9];
    const int* dst_dg = (const int*)d_in[10];
    const int* src_gd = (const int*)d_in[11];
    const int* dst_gd = (const int*)d_in[12];
    const int* src_gg = (const int*)d_in[13];
    const int* dst_gg = (const int*)d_in[14];
    float* out = (float*)d_out;

    const int n_edges = in_sizes[7];  // all four relations share E
    const int eb = (n_edges + 255) / 256;

    zero_cnt_kernel<<<(TOT + 255) / 256, 256>>>();
    gemm_kernel<<<dim3(NN / 32, 2), 256>>>(xd, xg, Wdd, Wdg, Wgd, Wgg);
    // slots: 0=(src_dd,dst_dd) 1=(src_gd,dst_gd) 2=(src_dg,dst_dg) 3=(src_gg,dst_gg)
    hist_kernel<<<dim3(eb, 4), 256>>>(dst_dd, dst_gd, dst_dg, dst_gg, n_edges);
    scan_blocks_kernel<<<NB, 1024>>>();
    scan_partials_kernel<<<1, 512>>>();
    add_base_kernel<<<(TOT + 255) / 256, 256>>>();
    scatter_perm_kernel<<<dim3(eb, 4), 256>>>(src_dd, dst_dd, src_gd, dst_gd,
                                              src_dg, dst_dg, src_gg, dst_gg, n_edges);
    gather_kernel<<<dim3(NN / 16, 2), 256>>>(bias, out);
}

// round 6
// speedup vs baseline: 2.2719x; 1.2407x over previous
#include <cuda_runtime.h>

#define NN 100000
#define DD 64
#define EMAX 800000
#define TOT (4 * NN)              // total count slots
#define NB ((TOT + 1023) / 1024)  // scan blocks = 391

// Scratch (static device globals; no runtime allocation).
// slot layout (by dst): 0=dd(drug) 1=gd(drug) 2=dg(gene) 3=gg(gene)
__device__ int g_cnt[TOT];           // per-(slot,dst) degree
__device__ int g_incl[TOT];          // block-inclusive scan
__device__ int g_base[TOT];          // exclusive offsets; after scatter_perm = end offsets
__device__ int g_bsum[512];          // per-block totals
__device__ int g_bbase[512];         // exclusive block bases
__device__ int g_psrc[4ull * EMAX];  // src indices sorted by (slot, dst)

// ---------------------------------------------------------------------------
__global__ void zero_cnt_kernel() {
    int i = blockIdx.x * blockDim.x + threadIdx.x;
    if (i < TOT) g_cnt[i] = 0;
}

// ---------------------------------------------------------------------------
// Counting sort, step 1: per-(slot,dst) histogram.
// ---------------------------------------------------------------------------
__global__ __launch_bounds__(256) void hist_kernel(
    const int* __restrict__ dst0, const int* __restrict__ dst1,
    const int* __restrict__ dst2, const int* __restrict__ dst3,
    int n_edges) {
    int e = blockIdx.x * 256 + threadIdx.x;
    if (e >= n_edges) return;
    const int slot = blockIdx.y;
    const int* dst = (slot == 0) ? dst0 : (slot == 1) ? dst1 : (slot == 2) ? dst2 : dst3;
    atomicAdd(&g_cnt[slot * NN + __ldg(dst + e)], 1);
}

// ---------------------------------------------------------------------------
// Step 2a: per-block inclusive scan (1024 elems/block) + block totals.
// ---------------------------------------------------------------------------
__global__ __launch_bounds__(1024) void scan_blocks_kernel() {
    __shared__ int s[1024];
    const int tid = threadIdx.x;
    const int i = blockIdx.x * 1024 + tid;
    int v = (i < TOT) ? g_cnt[i] : 0;
    s[tid] = v;
    __syncthreads();
#pragma unroll
    for (int off = 1; off < 1024; off <<= 1) {
        int t = (tid >= off) ? s[tid - off] : 0;
        __syncthreads();
        s[tid] += t;
        __syncthreads();
    }
    if (i < TOT) g_incl[i] = s[tid];
    if (tid == 1023) g_bsum[blockIdx.x] = s[1023];
}

// Step 2b: scan the 391 block totals (single block) -> exclusive block bases.
__global__ __launch_bounds__(512) void scan_partials_kernel() {
    __shared__ int s[512];
    const int tid = threadIdx.x;
    int v = (tid < NB) ? g_bsum[tid] : 0;
    s[tid] = v;
    __syncthreads();
#pragma unroll
    for (int off = 1; off < 512; off <<= 1) {
        int t = (tid >= off) ? s[tid - off] : 0;
        __syncthreads();
        s[tid] += t;
        __syncthreads();
    }
    g_bbase[tid] = s[tid] - v;  // exclusive
}

// Step 2c: global exclusive offset per slot-index.
__global__ __launch_bounds__(256) void add_base_kernel() {
    int i = blockIdx.x * 256 + threadIdx.x;
    if (i >= TOT) return;
    g_base[i] = g_bbase[i >> 10] + g_incl[i] - g_cnt[i];
}

// ---------------------------------------------------------------------------
// Step 3: scatter src indices into dst-sorted order. Afterwards g_base[idx]
// holds the END offset of segment idx (start = end - g_cnt[idx]).
// ---------------------------------------------------------------------------
__global__ __launch_bounds__(256) void scatter_perm_kernel(
    const int* __restrict__ src0, const int* __restrict__ dst0,
    const int* __restrict__ src1, const int* __restrict__ dst1,
    const int* __restrict__ src2, const int* __restrict__ dst2,
    const int* __restrict__ src3, const int* __restrict__ dst3,
    int n_edges) {
    int e = blockIdx.x * 256 + threadIdx.x;
    if (e >= n_edges) return;
    const int slot = blockIdx.y;
    const int* src; const int* dst;
    switch (slot) {
        case 0:  src = src0; dst = dst0; break;
        case 1:  src = src1; dst = dst1; break;
        case 2:  src = src2; dst = dst2; break;
        default: src = src3; dst = dst3; break;
    }
    const int s = __ldg(src + e);
    const int d = __ldg(dst + e);
    int pos = atomicAdd(&g_base[slot * NN + d], 1);
    g_psrc[pos] = s;
}

// ---------------------------------------------------------------------------
// f32x2 packed-FMA helpers (Blackwell).
// ---------------------------------------------------------------------------
__device__ __forceinline__ unsigned long long pk2(float lo, float hi) {
    unsigned long long r;
    asm("mov.b64 %0, {%1, %2};" : "=l"(r) : "f"(lo), "f"(hi));
    return r;
}
__device__ __forceinline__ void fma2(unsigned long long& acc,
                                     unsigned long long a, unsigned long long b) {
    asm("fma.rn.f32x2 %0, %1, %2, %0;" : "+l"(acc) : "l"(a), "l"(b));
}
__device__ __forceinline__ float2 up2(unsigned long long v) {
    float2 f;
    asm("mov.b64 {%0, %1}, %2;" : "=f"(f.x), "=f"(f.y) : "l"(v));
    return f;
}
__device__ __forceinline__ float4 shfl4(float4 v, int src) {
    float4 r;
    r.x = __shfl_sync(0xffffffffu, v.x, src, 16);
    r.y = __shfl_sync(0xffffffffu, v.y, src, 16);
    r.z = __shfl_sync(0xffffffffu, v.z, src, 16);
    r.w = __shfl_sync(0xffffffffu, v.w, src, 16);
    return r;
}

// ---------------------------------------------------------------------------
// Fused pull-gather + per-node 64x64 GEMM + bias + relu + output.
// Linearity: sum(x[src]) / deg @ W == GraphConv(norm='right').
// 16 lanes per node, 4 nodes per lane-group (amortizes W LDS 4x).
// Lane l owns feature chunk [4l, 4l+4) of both the aggregate and the output.
// ---------------------------------------------------------------------------
__global__ __launch_bounds__(256) void gather_gemm_kernel(
    const float* __restrict__ xd, const float* __restrict__ xg,
    const float* __restrict__ Wdd, const float* __restrict__ Wdg,
    const float* __restrict__ Wgd, const float* __restrict__ Wgg,
    const float* __restrict__ bias, float* __restrict__ out) {
    __shared__ float Wsm[2][64 * 64];  // [rel][k*64 + c], 32 KB

    const int t = blockIdx.y;  // 0=drug dst, 1=gene dst
    const int tid = threadIdx.x;
    const int lane = tid & 15;
    const int group = tid >> 4;                     // 0..15
    const int node0 = blockIdx.x * 64 + group * 4;  // 4 nodes per group

    // Load both W's for this dst type. rel0 src = x_drug, rel1 src = x_gene.
    //   t=0: rel0=(slot0, W_dd), rel1=(slot1, W_gd)
    //   t=1: rel0=(slot2, W_dg), rel1=(slot3, W_gg)
    const float* W0 = t ? Wdg : Wdd;
    const float* W1 = t ? Wgg : Wgd;
    for (int i = tid; i < 1024; i += 256) {
        reinterpret_cast<float4*>(Wsm[0])[i] = reinterpret_cast<const float4*>(W0)[i];
        reinterpret_cast<float4*>(Wsm[1])[i] = reinterpret_cast<const float4*>(W1)[i];
    }
    __syncthreads();

    unsigned long long res01[4], res23[4];
    const unsigned long long z = pk2(0.f, 0.f);
#pragma unroll
    for (int n = 0; n < 4; n++) { res01[n] = z; res23[n] = z; }

#pragma unroll 1
    for (int r = 0; r < 2; r++) {
        const float* x = r ? xg : xd;
        const int slot = 2 * t + r;

        // ---- gather + normalize: a[n] = (sum_e x[src]) / deg, lane's chunk
        float4 a[4];
#pragma unroll
        for (int n = 0; n < 4; n++) {
            a[n] = make_float4(0.f, 0.f, 0.f, 0.f);
            const int node = node0 + n;
            if (node >= NN) continue;
            const int idx = slot * NN + node;
            const int deg = __ldg(g_cnt + idx);
            const int end = __ldg(g_base + idx);
#pragma unroll 2
            for (int e = end - deg; e < end; e++) {
                int s = __ldg(g_psrc + e);
                float4 v = *reinterpret_cast<const float4*>(x + (size_t)s * DD + 4 * lane);
                a[n].x += v.x; a[n].y += v.y; a[n].z += v.z; a[n].w += v.w;
            }
            const float inv = 1.f / (float)max(deg, 1);
            a[n].x *= inv; a[n].y *= inv; a[n].z *= inv; a[n].w *= inv;
        }

        // ---- mini-GEMM: res[n][c] += sum_k a[n][k] * W[k][c], c = lane cols
        const float* Wr = Wsm[r];
#pragma unroll
        for (int kl = 0; kl < 16; kl++) {
            float4 av[4];
#pragma unroll
            for (int n = 0; n < 4; n++) av[n] = shfl4(a[n], kl);
#pragma unroll
            for (int j = 0; j < 4; j++) {
                const int k = 4 * kl + j;
                float4 w = *reinterpret_cast<const float4*>(Wr + k * 64 + 4 * lane);
                unsigned long long w01 = pk2(w.x, w.y);
                unsigned long long w23 = pk2(w.z, w.w);
#pragma unroll
                for (int n = 0; n < 4; n++) {
                    float s = (j == 0) ? av[n].x : (j == 1) ? av[n].y
                            : (j == 2) ? av[n].z : av[n].w;
                    unsigned long long ss = pk2(s, s);
                    fma2(res01[n], ss, w01);
                    fma2(res23[n], ss, w23);
                }
            }
        }
    }

    // ---- bias + relu + store
    const float4 b = reinterpret_cast<const float4*>(bias)[lane];
#pragma unroll
    for (int n = 0; n < 4; n++) {
        const int node = node0 + n;
        if (node >= NN) continue;
        float2 lo = up2(res01[n]);
        float2 hi = up2(res23[n]);
        float4 o;
        o.x = fmaxf(lo.x + b.x, 0.f);
        o.y = fmaxf(lo.y + b.y, 0.f);
        o.z = fmaxf(hi.x + b.z, 0.f);
        o.w = fmaxf(hi.y + b.w, 0.f);
        *reinterpret_cast<float4*>(out + (size_t)t * NN * DD + (size_t)node * DD + 4 * lane) = o;
    }
}

// ---------------------------------------------------------------------------
extern "C" void kernel_launch(void* const* d_in, const int* in_sizes, int n_in,
                              void* d_out, int out_size) {
    const float* xd   = (const float*)d_in[0];
    const float* xg   = (const float*)d_in[1];
    const float* Wdd  = (const float*)d_in[2];
    const float* Wdg  = (const float*)d_in[3];
    const float* Wgd  = (const float*)d_in[4];
    const float* Wgg  = (const float*)d_in[5];
    const float* bias = (const float*)d_in[6];
    const int* src_dd = (const int*)d_in[7];
    const int* dst_dd = (const int*)d_in[8];
    const int* src_dg = (const int*)d_in[9];
    const int* dst_dg = (const int*)d_in[10];
    const int* src_gd = (const int*)d_in[11];
    const int* dst_gd = (const int*)d_in[12];
    const int* src_gg = (const int*)d_in[13];
    const int* dst_gg = (const int*)d_in[14];
    float* out = (float*)d_out;

    const int n_edges = in_sizes[7];  // all four relations share E
    const int eb = (n_edges + 255) / 256;

    zero_cnt_kernel<<<(TOT + 255) / 256, 256>>>();
    // slots: 0=(src_dd,dst_dd) 1=(src_gd,dst_gd) 2=(src_dg,dst_dg) 3=(src_gg,dst_gg)
    hist_kernel<<<dim3(eb, 4), 256>>>(dst_dd, dst_gd, dst_dg, dst_gg, n_edges);
    scan_blocks_kernel<<<NB, 1024>>>();
    scan_partials_kernel<<<1, 512>>>();
    add_base_kernel<<<(TOT + 255) / 256, 256>>>();
    scatter_perm_kernel<<<dim3(eb, 4), 256>>>(src_dd, dst_dd, src_gd, dst_gd,
                                              src_dg, dst_dg, src_gg, dst_gg, n_edges);
    gather_gemm_kernel<<<dim3((NN + 63) / 64, 2), 256>>>(xd, xg, Wdd, Wdg, Wgd, Wgg,
                                                         bias, out);
}